// round 7
// baseline (speedup 1.0000x reference)
#include <cuda_runtime.h>
#include <cstdint>

#define SEQN 65536
#define HN   128
#define G4   512   // 4*H

typedef unsigned long long u64;

// Scratch (device globals: allocation-free per harness rules)
__device__ float g_GA[(size_t)SEQN * G4];   // x@WA1^T + bA1 + bA2
__device__ float g_HB[(size_t)SEQN * HN];   // hB per step (fc input)

// ---------------------------------------------------------------------------
// helpers
// ---------------------------------------------------------------------------
__device__ __forceinline__ float tanhfast(float x) {
    float y;
    asm("tanh.approx.f32 %0, %1;" : "=f"(y) : "f"(x));
    return y;
}
__device__ __forceinline__ float sigmfast(float x) {
    return fmaf(tanhfast(0.5f * x), 0.5f, 0.5f);
}

__device__ __forceinline__ uint32_t mapa_u32(const void* p, int rank) {
    uint32_t a = (uint32_t)__cvta_generic_to_shared(p), r;
    asm("mapa.shared::cluster.u32 %0, %1, %2;" : "=r"(r) : "r"(a), "r"(rank));
    return r;
}

#define ST_CLUSTER_F32(addr, v) \
    asm volatile("st.shared::cluster.f32 [%0], %1;" :: "r"(addr), "f"(v) : "memory")

#define ST_FLAG_RELEASE(addr, v) \
    asm volatile("st.release.cluster.shared::cluster.b32 [%0], %1;" \
                 :: "r"(addr), "r"(v) : "memory")

#define FENCE_ACQREL_CLUSTER() asm volatile("fence.acq_rel.cluster;" ::: "memory")

__device__ __forceinline__ int ld_flag_acquire(uint32_t addr) {
    int f;
    asm volatile("ld.acquire.cluster.shared::cta.b32 %0, [%1];"
                 : "=r"(f) : "r"(addr) : "memory");
    return f;
}

#define FMA2(acc, w, h) \
    asm("fma.rn.f32x2 %0, %1, %2, %0;" : "+l"(acc) : "l"(w), "l"(h))

#define CLUSTER_SYNC_()                                                        \
    do {                                                                       \
        asm volatile("barrier.cluster.arrive.aligned;" ::: "memory");          \
        asm volatile("barrier.cluster.wait.aligned;"   ::: "memory");          \
    } while (0)

// ---------------------------------------------------------------------------
// Kernel 1: GA[t, 512] = x[t] @ WA1^T + bA1 + bA2
// ---------------------------------------------------------------------------
__global__ void __launch_bounds__(128) ga_kernel(const float* __restrict__ x,
                                                 const float* __restrict__ W,
                                                 const float* __restrict__ b1,
                                                 const float* __restrict__ b2) {
    __shared__ float xs[64 * 128];
    const int tid = threadIdx.x;
    const int row = (blockIdx.y << 7) + tid;

    float4 w[32];
    const float4* wg = (const float4*)(W + (size_t)row * 128);
#pragma unroll
    for (int k = 0; k < 32; k++) w[k] = wg[k];
    const float bias = b1[row] + b2[row];

    const int t0 = blockIdx.x * 64;
    const float4* xg = (const float4*)(x + (size_t)t0 * 128);
    float4* xs4 = (float4*)xs;
#pragma unroll
    for (int i = 0; i < 16; i++) xs4[tid + (i << 7)] = xg[tid + (i << 7)];
    __syncthreads();

    for (int tt = 0; tt < 64; tt++) {
        const float4* hx = (const float4*)(xs + tt * 128);
        float a0 = 0.f, a1 = 0.f, a2 = 0.f, a3 = 0.f;
#pragma unroll
        for (int k = 0; k < 32; k++) {
            float4 h = hx[k];
            a0 = fmaf(w[k].x, h.x, a0);
            a1 = fmaf(w[k].y, h.y, a1);
            a2 = fmaf(w[k].z, h.z, a2);
            a3 = fmaf(w[k].w, h.w, a3);
        }
        g_GA[(size_t)(t0 + tt) * G4 + row] = (a0 + a1) + (a2 + a3) + bias;
    }
}

// ---------------------------------------------------------------------------
// Kernel 2: pipelined recurrence (B one tick behind A). 8-CTA cluster, 384 thr.
// NO cluster barrier in the loop. Sync = monotonic tick flags:
//   tick t: [t>0] each warp's lanes 0-7 ld.acquire-spin on s_flag[0..7] until
//   >= t-1  ->  matvec (FFMA2) reads buf[t&1]  ->  bar.sync  ->  warp 0:
//   lanes 0-15 cell A(t), lanes 16-31 cell B(t-1), st.shared::cluster h into
//   buf[(t+1)&1] on all 8 ranks, fence.acq_rel.cluster, __syncwarp, lanes 0-7
//   st.release s_flag[myrank]=t on each rank.
// Buffer safety: writes of buf[(t+1)&1] at tick t+2 are gated by flags>=t+1,
// which each CTA releases only after its t+1 matvec finished reading that buf.
// ---------------------------------------------------------------------------
__global__ void __cluster_dims__(8, 1, 1) __launch_bounds__(384, 1)
recur_kernel(const float* __restrict__ WA2, const float* __restrict__ WB1,
             const float* __restrict__ WB2, const float* __restrict__ bB1,
             const float* __restrict__ bB2, const float* __restrict__ hA0,
             const float* __restrict__ cA0, const float* __restrict__ hB0,
             const float* __restrict__ cB0, float* __restrict__ out,
             int write_states) {
    __shared__ alignas(16) float s_hA[2][HN];
    __shared__ alignas(16) float s_hB[2][HN];
    __shared__ float s_uA[64];   // WA2 dots (+GA)
    __shared__ float s_wB[64];   // WB1 dots
    __shared__ float s_vB[64];   // WB2 dots
    __shared__ float s_bb[64];   // bB1+bB2
    __shared__ int   s_flag[8];  // last tick published by rank i

    const int c    = blockIdx.x;
    const int tid  = threadIdx.x;
    const int lane = tid & 31;
    const int rs   = tid >> 1;      // 0..191
    const int half = tid & 1;
    const int mat  = rs >> 6;       // 0:WA2 1:WB1 2:WB2
    const int r    = rs & 63;
    const int grow = ((r >> 4) << 7) + (c << 4) + (r & 15);

    // ---- weights as packed f32x2 ----
    const float* Wp = (mat == 0) ? WA2 : (mat == 1) ? WB1 : WB2;
    u64 wv[32];
    {
        const ulonglong2* wg = (const ulonglong2*)(Wp + (size_t)grow * 128 + half * 64);
#pragma unroll
        for (int k = 0; k < 16; k++) { ulonglong2 q = wg[k]; wv[2*k] = q.x; wv[2*k+1] = q.y; }
    }

    // ---- init SMEM ----
    if (tid < 64) {
        const int gr = ((tid >> 4) << 7) + (c << 4) + (tid & 15);
        s_bb[tid] = bB1[gr] + bB2[gr];
    }
    if (tid < HN) {
        s_hA[0][tid] = hA0[tid];   // read at tick 0
        s_hB[0][tid] = 0.f;        // discarded read at tick 0
        s_hB[1][tid] = hB0[tid];   // read at tick 1
    }
    if (tid < 8) s_flag[tid] = -1;

    // ---- activation-warp (warp 0) state ----
    float cAr = 0.f, cBr = 0.f, hB_init = 0.f;
    uint32_t pdst[2][8];           // [buffer][rank] for my h slot
    uint32_t fdst = 0;             // lanes 0-7: &s_flag[c] on rank `lane`
    if (tid < 32) {
        const int jj = lane & 15;
        const int j  = (c << 4) + jj;
        if (lane < 16) {
            cAr = cA0[j];
        } else {
            cBr = cB0[j];
            hB_init = hB0[j];
        }
#pragma unroll
        for (int buf = 0; buf < 2; buf++) {
            const float* base = (lane < 16) ? &s_hA[buf][j] : &s_hB[buf][j];
#pragma unroll
            for (int rk = 0; rk < 8; rk++) pdst[buf][rk] = mapa_u32(base, rk);
        }
        if (lane < 8) fdst = mapa_u32(&s_flag[c], lane);
    }
    // every warp: local flag address for polling (lanes 0-7)
    const uint32_t floc =
        (uint32_t)__cvta_generic_to_shared(&s_flag[lane & 7]);

    __syncthreads();
    CLUSTER_SYNC_();   // all CTAs' SMEM + flags initialized

    // ---- GA prefetch, distance 2 (mat==0 half==0 lanes) ----
    const bool is_ga = (mat == 0) && (half == 0);
    float ga0 = 0.f, ga1 = 0.f;
    if (is_ga) {
        ga0 = g_GA[grow];
        ga1 = __ldg(&g_GA[(size_t)G4 + grow]);
    }

    const size_t OH = (size_t)SEQN * HN;

    for (int t = 0; t <= SEQN; t++) {
        const int pb = t & 1;

        // ===== wait for h(t-1) from all 8 CTAs =====
        if (t > 0) {
            const int want = t - 1;
            if (lane < 8) {
                while (ld_flag_acquire(floc) < want) { }
            }
            __syncwarp();
        }

        float ga2 = 0.f;
        if (is_ga && t + 2 < SEQN)
            ga2 = __ldg(&g_GA[(size_t)(t + 2) * G4 + grow]);

        // ===== merged matvec (FFMA2): u=WA2*hA(t-1), w=WB1*hA(t-1), v=WB2*hB(t-2)
        {
            const float* hsrc = (mat == 2) ? s_hB[pb] : s_hA[pb];
            const ulonglong2* hv = (const ulonglong2*)(hsrc + half * 64);
            u64 a0 = 0ULL, a1 = 0ULL;
#pragma unroll
            for (int k = 0; k < 16; k++) {
                ulonglong2 h2 = hv[k];
                FMA2(a0, wv[2*k],     h2.x);
                FMA2(a1, wv[2*k + 1], h2.y);
            }
            float2 f0 = *(float2*)&a0, f1 = *(float2*)&a1;
            float s = (f0.x + f0.y) + (f1.x + f1.y);
            s += __shfl_down_sync(0xffffffffu, s, 1);
            if (half == 0) {
                if (mat == 0)      s_uA[r] = s + ga0;
                else if (mat == 1) s_wB[r] = s;
                else               s_vB[r] = s;
            }
        }
        __syncthreads();

        // ===== activation warp (warp 0): cell A(t) | cell B(t-1) =====
        if (tid < 32) {
            float h_val = 0.f, cn = 0.f;
            if (lane < 16) {
                if (t < SEQN) {
                    const float gi = s_uA[lane];
                    const float gf = s_uA[16 + lane];
                    const float gg = s_uA[32 + lane];
                    const float go = s_uA[48 + lane];
                    cn = sigmfast(gf) * cAr + sigmfast(gi) * tanhfast(gg);
                    cAr = cn;
                    h_val = sigmfast(go) * tanhfast(cn);
                }
            } else {
                const int ln = lane - 16;
                if (t == 0) {
                    h_val = hB_init;
                } else {
                    const float gi = s_wB[ln]      + s_vB[ln]      + s_bb[ln];
                    const float gf = s_wB[16 + ln] + s_vB[16 + ln] + s_bb[16 + ln];
                    const float gg = s_wB[32 + ln] + s_vB[32 + ln] + s_bb[32 + ln];
                    const float go = s_wB[48 + ln] + s_vB[48 + ln] + s_bb[48 + ln];
                    cn = sigmfast(gf) * cBr + sigmfast(gi) * tanhfast(gg);
                    cBr = cn;
                    h_val = sigmfast(go) * tanhfast(cn);
                }
            }

            if (t < SEQN) {
                // broadcast h into buf[(t+1)&1] on all ranks, then publish tick
#pragma unroll
                for (int rk = 0; rk < 8; rk++) ST_CLUSTER_F32(pdst[pb ^ 1][rk], h_val);
                FENCE_ACQREL_CLUSTER();
                __syncwarp();
                if (lane < 8) ST_FLAG_RELEASE(fdst, t);
            }

            // GMEM side-effects (off critical path)
            if (lane >= 16 && t >= 1) {
                const int j = (c << 4) + (lane - 16);
                g_HB[(size_t)(t - 1) * HN + j] = h_val;
                if (write_states && t == SEQN) {
                    out[OH + 2 * HN + j] = h_val;
                    out[OH + 3 * HN + j] = cn;
                }
            }
            if (lane < 16 && write_states && t == SEQN - 1) {
                const int j = (c << 4) + lane;
                out[OH + j]      = h_val;
                out[OH + HN + j] = cn;
            }
        }

        if (is_ga) { ga0 = ga1; ga1 = ga2; }
    }

    CLUSTER_SYNC_();   // keep peers' SMEM alive until all remote traffic done
}

// ---------------------------------------------------------------------------
// Kernel 3: logits[t] = hB[t] @ Wfc^T + bfc
// ---------------------------------------------------------------------------
__global__ void __launch_bounds__(128) fc_kernel(const float* __restrict__ W,
                                                 const float* __restrict__ b,
                                                 float* __restrict__ out) {
    __shared__ float hs[64 * 128];
    const int tid = threadIdx.x;

    float4 w[32];
    const float4* wg = (const float4*)(W + (size_t)tid * 128);
#pragma unroll
    for (int k = 0; k < 32; k++) w[k] = wg[k];
    const float bias = b[tid];

    const int t0 = blockIdx.x * 64;
    const float4* hg = (const float4*)(g_HB + (size_t)t0 * 128);
    float4* hs4 = (float4*)hs;
#pragma unroll
    for (int i = 0; i < 16; i++) hs4[tid + (i << 7)] = hg[tid + (i << 7)];
    __syncthreads();

    for (int tt = 0; tt < 64; tt++) {
        const float4* hx = (const float4*)(hs + tt * 128);
        float a0 = 0.f, a1 = 0.f, a2 = 0.f, a3 = 0.f;
#pragma unroll
        for (int k = 0; k < 32; k++) {
            float4 h = hx[k];
            a0 = fmaf(w[k].x, h.x, a0);
            a1 = fmaf(w[k].y, h.y, a1);
            a2 = fmaf(w[k].z, h.z, a2);
            a3 = fmaf(w[k].w, h.w, a3);
        }
        out[(size_t)(t0 + tt) * 128 + tid] = (a0 + a1) + (a2 + a3) + bias;
    }
}

// ---------------------------------------------------------------------------
// launch
// ---------------------------------------------------------------------------
extern "C" void kernel_launch(void* const* d_in, const int* in_sizes, int n_in,
                              void* d_out, int out_size) {
    const float* x   = (const float*)d_in[0];
    const float* hA0 = (const float*)d_in[1];
    const float* cA0 = (const float*)d_in[2];
    const float* hB0 = (const float*)d_in[3];
    const float* cB0 = (const float*)d_in[4];
    const float* WA1 = (const float*)d_in[5];
    const float* bA1 = (const float*)d_in[6];
    const float* WA2 = (const float*)d_in[7];
    const float* bA2 = (const float*)d_in[8];
    const float* WB1 = (const float*)d_in[9];
    const float* bB1 = (const float*)d_in[10];
    const float* WB2 = (const float*)d_in[11];
    const float* bB2 = (const float*)d_in[12];
    const float* Wfc = (const float*)d_in[13];
    const float* bfc = (const float*)d_in[14];
    float* out = (float*)d_out;

    const int write_states = (out_size >= SEQN * HN + 4 * HN) ? 1 : 0;

    ga_kernel<<<dim3(SEQN / 64, 4), 128>>>(x, WA1, bA1, bA2);
    recur_kernel<<<8, 384>>>(WA2, WB1, WB2, bB1, bB2, hA0, cA0, hB0, cB0, out,
                             write_states);
    fc_kernel<<<SEQN / 64, 128>>>(Wfc, bfc, out);
}

// round 8
// speedup vs baseline: 1.7599x; 1.7599x over previous
#include <cuda_runtime.h>
#include <cstdint>

#define SEQN 65536
#define HN   128
#define G4   512   // 4*H

typedef unsigned long long u64;

// Scratch (device globals: allocation-free per harness rules)
__device__ float g_GA[(size_t)SEQN * G4];   // precomputed x@WA1^T + bA1 + bA2
__device__ float g_HB[(size_t)SEQN * HN];   // hB per step, consumed by fc GEMM

// ---------------------------------------------------------------------------
// helpers
// ---------------------------------------------------------------------------
__device__ __forceinline__ float tanhfast(float x) {
    float y;
    asm("tanh.approx.f32 %0, %1;" : "=f"(y) : "f"(x));
    return y;
}
__device__ __forceinline__ float sigmfast(float x) {
    return fmaf(tanhfast(0.5f * x), 0.5f, 0.5f);
}

__device__ __forceinline__ void st_remote_f32(float* p, int rank, float v) {
    uint32_t addr = (uint32_t)__cvta_generic_to_shared(p);
    uint32_t raddr;
    asm volatile("mapa.shared::cluster.u32 %0, %1, %2;" : "=r"(raddr) : "r"(addr), "r"(rank));
    asm volatile("st.shared::cluster.f32 [%0], %1;" :: "r"(raddr), "f"(v) : "memory");
}

#define FMA2(acc, w, h) \
    asm("fma.rn.f32x2 %0, %1, %2, %0;" : "+l"(acc) : "l"(w), "l"(h))

#define CLUSTER_ARRIVE_() asm volatile("barrier.cluster.arrive.aligned;" ::: "memory")
#define CLUSTER_WAIT_()   asm volatile("barrier.cluster.wait.aligned;"   ::: "memory")
#define CLUSTER_SYNC_()   do { CLUSTER_ARRIVE_(); CLUSTER_WAIT_(); } while (0)

// ---------------------------------------------------------------------------
// Kernel 1: GA[t, 512] = x[t] @ WA1^T + bA1 + bA2
// ---------------------------------------------------------------------------
__global__ void __launch_bounds__(128) ga_kernel(const float* __restrict__ x,
                                                 const float* __restrict__ W,
                                                 const float* __restrict__ b1,
                                                 const float* __restrict__ b2) {
    __shared__ float xs[64 * 128];
    const int tid = threadIdx.x;
    const int row = (blockIdx.y << 7) + tid;

    float4 w[32];
    const float4* wg = (const float4*)(W + (size_t)row * 128);
#pragma unroll
    for (int k = 0; k < 32; k++) w[k] = wg[k];
    const float bias = b1[row] + b2[row];

    const int t0 = blockIdx.x * 64;
    const float4* xg = (const float4*)(x + (size_t)t0 * 128);
    float4* xs4 = (float4*)xs;
#pragma unroll
    for (int i = 0; i < 16; i++) xs4[tid + (i << 7)] = xg[tid + (i << 7)];
    __syncthreads();

    for (int tt = 0; tt < 64; tt++) {
        const float4* hx = (const float4*)(xs + tt * 128);
        float a0 = 0.f, a1 = 0.f, a2 = 0.f, a3 = 0.f;
#pragma unroll
        for (int k = 0; k < 32; k++) {
            float4 h = hx[k];
            a0 = fmaf(w[k].x, h.x, a0);
            a1 = fmaf(w[k].y, h.y, a1);
            a2 = fmaf(w[k].z, h.z, a2);
            a3 = fmaf(w[k].w, h.w, a3);
        }
        g_GA[(size_t)(t0 + tt) * G4 + row] = (a0 + a1) + (a2 + a3) + bias;
    }
}

// ---------------------------------------------------------------------------
// Kernel 2: R2 champion skeleton + FFMA2 + tanh.approx.
// 8-CTA cluster, 384 threads. B one tick behind A; per tick: merged matvec
// (all three weight matrices, FFMA2), __syncthreads, parallel A/B activation
// warps, DSMEM h broadcast, ONE barrier.cluster (GA register rotate hidden
// between arrive and wait).
// ---------------------------------------------------------------------------
__global__ void __cluster_dims__(8, 1, 1) __launch_bounds__(384, 1)
recur_kernel(const float* __restrict__ WA2, const float* __restrict__ WB1,
             const float* __restrict__ WB2, const float* __restrict__ bB1,
             const float* __restrict__ bB2, const float* __restrict__ hA0,
             const float* __restrict__ cA0, const float* __restrict__ hB0,
             const float* __restrict__ cB0, float* __restrict__ out,
             int write_states) {
    __shared__ alignas(16) float s_hA[2][HN];
    __shared__ alignas(16) float s_hB[2][HN];
    __shared__ float s_uA[64];   // WA2 dots (+GA)
    __shared__ float s_wB[64];   // WB1 dots
    __shared__ float s_vB[64];   // WB2 dots
    __shared__ float s_bb[64];   // bB1+bB2

    const int c    = blockIdx.x;
    const int tid  = threadIdx.x;
    const int rs   = tid >> 1;      // 0..191
    const int half = tid & 1;
    const int mat  = rs >> 6;       // 0:WA2 1:WB1 2:WB2
    const int r    = rs & 63;
    const int grow = ((r >> 4) << 7) + (c << 4) + (r & 15);

    // ---- weights as packed f32x2 ----
    const float* Wp = (mat == 0) ? WA2 : (mat == 1) ? WB1 : WB2;
    u64 wv[32];
    {
        const ulonglong2* wg = (const ulonglong2*)(Wp + (size_t)grow * 128 + half * 64);
#pragma unroll
        for (int k = 0; k < 16; k++) { ulonglong2 q = wg[k]; wv[2*k] = q.x; wv[2*k+1] = q.y; }
    }

    // ---- init SMEM ----
    if (tid < 64) {
        const int gr = ((tid >> 4) << 7) + (c << 4) + (tid & 15);
        s_bb[tid] = bB1[gr] + bB2[gr];
    }
    if (tid < HN) {
        s_hA[0][tid] = hA0[tid];   // hA(-1), read at tick 0
        s_hB[1][tid] = hB0[tid];   // hB(-1), read at tick 1
        s_hB[0][tid] = 0.f;        // read (discarded) at tick 0
    }
    const bool isA = (tid < 16);
    const bool isB = (tid >= 32 && tid < 48);
    float cAr = 0.f, cBr = 0.f, hB_init = 0.f;
    if (isA) cAr = cA0[(c << 4) + tid];
    if (isB) { cBr = cB0[(c << 4) + (tid - 32)]; hB_init = hB0[(c << 4) + (tid - 32)]; }
    __syncthreads();

    // ---- GA prefetch, distance 2 (mat==0 half==0 lanes) ----
    const bool is_ga = (mat == 0) && (half == 0);
    float ga0 = 0.f, ga1 = 0.f;
    if (is_ga) {
        ga0 = g_GA[grow];
        ga1 = __ldg(&g_GA[(size_t)G4 + grow]);
    }

    const size_t OH = (size_t)SEQN * HN;   // state offset in d_out

    for (int t = 0; t <= SEQN; t++) {
        const int pb = t & 1;

        float ga2 = 0.f;
        if (is_ga && t + 2 < SEQN)
            ga2 = __ldg(&g_GA[(size_t)(t + 2) * G4 + grow]);

        // ===== merged matvec (FFMA2): u=WA2*hA(t-1), w=WB1*hA(t-1), v=WB2*hB(t-2)
        {
            const float* hsrc = (mat == 2) ? s_hB[pb] : s_hA[pb];
            const ulonglong2* hv = (const ulonglong2*)(hsrc + half * 64);
            u64 a0 = 0ULL, a1 = 0ULL;
#pragma unroll
            for (int k = 0; k < 16; k++) {
                ulonglong2 h2 = hv[k];
                FMA2(a0, wv[2*k],     h2.x);
                FMA2(a1, wv[2*k + 1], h2.y);
            }
            float2 f0 = *(float2*)&a0, f1 = *(float2*)&a1;
            float s = (f0.x + f0.y) + (f1.x + f1.y);
            s += __shfl_down_sync(0xffffffffu, s, 1);
            if (half == 0) {
                if (mat == 0)      s_uA[r] = s + ga0;
                else if (mat == 1) s_wB[r] = s;
                else               s_vB[r] = s;
            }
        }
        __syncthreads();

        // ===== cell A activation (step t), warp 0 lanes 0-15 =====
        if (isA && t < SEQN) {
            const float gi = s_uA[tid];
            const float gf = s_uA[16 + tid];
            const float gg = s_uA[32 + tid];
            const float go = s_uA[48 + tid];
            const float cn = sigmfast(gf) * cAr + sigmfast(gi) * tanhfast(gg);
            cAr = cn;
            const float h = sigmfast(go) * tanhfast(cn);
            const int j = (c << 4) + tid;
#pragma unroll
            for (int rk = 0; rk < 8; rk++) st_remote_f32(&s_hA[pb ^ 1][j], rk, h);
            if (write_states && t == SEQN - 1) {
                out[OH + j]      = h;
                out[OH + HN + j] = cn;
            }
        }

        // ===== cell B activation (step t-1), warp 1 lanes 0-15 =====
        if (isB) {
            const int ln = tid - 32;
            float h, cn = cBr;
            if (t == 0) {
                h = hB_init;
            } else {
                const float gi = s_wB[ln]      + s_vB[ln]      + s_bb[ln];
                const float gf = s_wB[16 + ln] + s_vB[16 + ln] + s_bb[16 + ln];
                const float gg = s_wB[32 + ln] + s_vB[32 + ln] + s_bb[32 + ln];
                const float go = s_wB[48 + ln] + s_vB[48 + ln] + s_bb[48 + ln];
                cn = sigmfast(gf) * cBr + sigmfast(gi) * tanhfast(gg);
                cBr = cn;
                h = sigmfast(go) * tanhfast(cn);
            }
            const int j = (c << 4) + ln;
            if (t < SEQN) {
#pragma unroll
                for (int rk = 0; rk < 8; rk++) st_remote_f32(&s_hB[pb ^ 1][j], rk, h);
            }
            if (t >= 1) {
                g_HB[(size_t)(t - 1) * HN + j] = h;
                if (write_states && t == SEQN) {
                    out[OH + 2 * HN + j] = h;
                    out[OH + 3 * HN + j] = cn;
                }
            }
        }

        CLUSTER_ARRIVE_();
        if (is_ga) { ga0 = ga1; ga1 = ga2; }   // hidden between arrive and wait
        CLUSTER_WAIT_();
    }
}

// ---------------------------------------------------------------------------
// Kernel 3: logits[t] = hB[t] @ Wfc^T + bfc
// ---------------------------------------------------------------------------
__global__ void __launch_bounds__(128) fc_kernel(const float* __restrict__ W,
                                                 const float* __restrict__ b,
                                                 float* __restrict__ out) {
    __shared__ float hs[64 * 128];
    const int tid = threadIdx.x;

    float4 w[32];
    const float4* wg = (const float4*)(W + (size_t)tid * 128);
#pragma unroll
    for (int k = 0; k < 32; k++) w[k] = wg[k];
    const float bias = b[tid];

    const int t0 = blockIdx.x * 64;
    const float4* hg = (const float4*)(g_HB + (size_t)t0 * 128);
    float4* hs4 = (float4*)hs;
#pragma unroll
    for (int i = 0; i < 16; i++) hs4[tid + (i << 7)] = hg[tid + (i << 7)];
    __syncthreads();

    for (int tt = 0; tt < 64; tt++) {
        const float4* hx = (const float4*)(hs + tt * 128);
        float a0 = 0.f, a1 = 0.f, a2 = 0.f, a3 = 0.f;
#pragma unroll
        for (int k = 0; k < 32; k++) {
            float4 h = hx[k];
            a0 = fmaf(w[k].x, h.x, a0);
            a1 = fmaf(w[k].y, h.y, a1);
            a2 = fmaf(w[k].z, h.z, a2);
            a3 = fmaf(w[k].w, h.w, a3);
        }
        out[(size_t)(t0 + tt) * 128 + tid] = (a0 + a1) + (a2 + a3) + bias;
    }
}

// ---------------------------------------------------------------------------
// launch
// inputs: 0 x, 1 hA, 2 cA, 3 hB, 4 cB, 5 WA1, 6 bA1, 7 WA2, 8 bA2,
//         9 WB1, 10 bB1, 11 WB2, 12 bB2, 13 Wfc, 14 bfc
// ---------------------------------------------------------------------------
extern "C" void kernel_launch(void* const* d_in, const int* in_sizes, int n_in,
                              void* d_out, int out_size) {
    const float* x   = (const float*)d_in[0];
    const float* hA0 = (const float*)d_in[1];
    const float* cA0 = (const float*)d_in[2];
    const float* hB0 = (const float*)d_in[3];
    const float* cB0 = (const float*)d_in[4];
    const float* WA1 = (const float*)d_in[5];
    const float* bA1 = (const float*)d_in[6];
    const float* WA2 = (const float*)d_in[7];
    const float* bA2 = (const float*)d_in[8];
    const float* WB1 = (const float*)d_in[9];
    const float* bB1 = (const float*)d_in[10];
    const float* WB2 = (const float*)d_in[11];
    const float* bB2 = (const float*)d_in[12];
    const float* Wfc = (const float*)d_in[13];
    const float* bfc = (const float*)d_in[14];
    float* out = (float*)d_out;

    const int write_states = (out_size >= SEQN * HN + 4 * HN) ? 1 : 0;

    ga_kernel<<<dim3(SEQN / 64, 4), 128>>>(x, WA1, bA1, bA2);
    recur_kernel<<<8, 384>>>(WA2, WB1, WB2, bB1, bB2, hA0, cA0, hB0, cB0, out,
                             write_states);
    fc_kernel<<<SEQN / 64, 128>>>(Wfc, bfc, out);
}